// round 4
// baseline (speedup 1.0000x reference)
#include <cuda_runtime.h>
#include <cuda_bf16.h>
#include <cstdint>

#define BB 16
#define NN 128
#define HD 128
#define ED 64
#define MD 128

typedef unsigned long long u64;
typedef unsigned int u32;

// Scratch: c1[b,j,m] = h[b,j]@W1 + bias ; c2[b,i,m] = h[b,i]@W2
__device__ float g_c1[BB * NN * MD];
__device__ float g_c2[BB * NN * MD];

// ---------------- smem layout (dynamic) ----------------
// adj_s: [0,512). W3 hi/lo: 64 rows x 272B. e hi/lo: 128 rows x 144B.
#define WH_OFF 1024
#define WL_OFF (WH_OFF + 64 * 272)          // 18432
#define EH_OFF (WL_OFF + 64 * 272)          // 35840
#define EL_OFF (EH_OFF + 128 * 144)         // 54272
#define SMEM_BYTES (EL_OFF + 128 * 144)     // 72704

__device__ __forceinline__ u32 smem_u32(const void* p) {
    u32 a;
    asm("{ .reg .u64 t; cvta.to.shared.u64 t, %1; cvt.u32.u64 %0, t; }"
        : "=r"(a) : "l"(p));
    return a;
}
__device__ __forceinline__ void ldsm_x4(u32 r[4], u32 addr) {
    asm volatile("ldmatrix.sync.aligned.m8n8.x4.shared.b16 {%0,%1,%2,%3}, [%4];"
                 : "=r"(r[0]), "=r"(r[1]), "=r"(r[2]), "=r"(r[3]) : "r"(addr));
}
__device__ __forceinline__ void ldsm_x4t(u32 r[4], u32 addr) {
    asm volatile("ldmatrix.sync.aligned.m8n8.x4.trans.shared.b16 {%0,%1,%2,%3}, [%4];"
                 : "=r"(r[0]), "=r"(r[1]), "=r"(r[2]), "=r"(r[3]) : "r"(addr));
}
__device__ __forceinline__ void mma_bf16(float c[4], const u32 a[4], u32 b0, u32 b1) {
    asm volatile(
        "mma.sync.aligned.m16n8k16.row.col.f32.bf16.bf16.f32 "
        "{%0,%1,%2,%3}, {%4,%5,%6,%7}, {%8,%9}, {%0,%1,%2,%3};"
        : "+f"(c[0]), "+f"(c[1]), "+f"(c[2]), "+f"(c[3])
        : "r"(a[0]), "r"(a[1]), "r"(a[2]), "r"(a[3]), "r"(b0), "r"(b1));
}
__device__ __forceinline__ u32 bf16x2_rn(float lo, float hi) {
    u32 r;
    asm("cvt.rn.bf16x2.f32 %0, %1, %2;" : "=r"(r) : "f"(hi), "f"(lo));
    return r;
}

// ---------------- Kernel 1: precompute c1, c2 ----------------
// 256 blocks x 128 threads; each block handles 8 rows of h (row = b*N+n).
__global__ __launch_bounds__(128) void precompute_kernel(
    const float* __restrict__ h, const float* __restrict__ W,
    const float* __restrict__ bias) {
    __shared__ float h_s[8 * 128];
    const int t = threadIdx.x;
    const int rb = blockIdx.x * 8;

#pragma unroll
    for (int q = 0; q < 8; q++)
        h_s[q * 128 + t] = h[(size_t)(rb + q) * HD + t];
    __syncthreads();

    float acc1[8], acc2[8];
#pragma unroll
    for (int r = 0; r < 8; r++) { acc1[r] = 0.f; acc2[r] = 0.f; }

#pragma unroll 4
    for (int k = 0; k < HD; k++) {
        const float w1 = W[(size_t)k * MD + t];
        const float w2 = W[(size_t)(HD + k) * MD + t];
#pragma unroll
        for (int r = 0; r < 8; r++) {
            const float hv = h_s[r * 128 + k];
            acc1[r] = fmaf(hv, w1, acc1[r]);
            acc2[r] = fmaf(hv, w2, acc2[r]);
        }
    }

    const float bv = bias[t];
#pragma unroll
    for (int r = 0; r < 8; r++) {
        g_c1[(size_t)(rb + r) * MD + t] = acc1[r] + bv;
        g_c2[(size_t)(rb + r) * MD + t] = acc2[r];
    }
}

// ---------------- Kernel 2: persistent mma.sync message kernel ----------------
// Grid 444 (3 CTAs/SM), 128 threads (4 warps). Tile = (b,i):
//   D[j,m] = sum_k e[b,i,j,k] * W3[k,m]   (bf16 hi/lo 3-pass HMMA)
//   out[b,i,j,m] = (D + c1[b,j,m] + c2[b,i,m]) * adj[b,i,j]
// Warp w owns j in [32w, 32w+32). m processed in 4 chunks of 32.
__global__ __launch_bounds__(128, 3) void message_kernel(
    const float* __restrict__ e, const float* __restrict__ adj,
    const float* __restrict__ W, float* __restrict__ out) {
    extern __shared__ char sm[];
    const u32 smb = smem_u32(sm);
    float* adj_s = reinterpret_cast<float*>(sm);
    const int t = threadIdx.x;
    const int warp = t >> 5, lane = t & 31;
    const int gid = lane >> 2, tig = lane & 3;

    // --- one-time: zero e tiles (finite-stale safety) ---
    {
        u64* z = reinterpret_cast<u64*>(sm + EH_OFF);
        for (int i = t; i < (128 * 144 * 2) / 8; i += 128) z[i] = 0ull;
    }
    // --- one-time: convert W3 -> bf16 hi/lo smem tiles [k][m], stride 272B ---
    for (int it = 0; it < 64; it++) {
        const float v = W[(size_t)(2 * HD + it) * MD + t];
        const u32 bv = __float_as_uint(v);
        const float lo = v - __uint_as_float(bv & 0xFFFF0000u);
        *reinterpret_cast<unsigned short*>(sm + WH_OFF + it * 272 + t * 2) =
            (unsigned short)(bv >> 16);
        *reinterpret_cast<unsigned short*>(sm + WL_OFF + it * 272 + t * 2) =
            __bfloat16_as_ushort(__float2bfloat16_rn(lo));
    }
    __syncthreads();

    // Per-lane ldmatrix base addresses (row part).
    const u32 rowA = smb + EH_OFF + (u32)(lane & 15) * 144 + (u32)(lane >> 4) * 16;
    const u32 rowB = smb + WH_OFF + (u32)(lane & 15) * 272 + (u32)(lane >> 4) * 16;
    const int j0 = warp * 32;

    for (int tile = blockIdx.x; tile < BB * NN; tile += gridDim.x) {
        const int bi = tile;
        const int b = tile >> 7;

        __syncthreads();  // protect adj_s / e_s reuse from previous tile
        if (t < NN) adj_s[t] = __ldg(&adj[(size_t)bi * NN + t]);
        __syncthreads();

        // Convert active e rows -> hi/lo bf16 smem (stride 144B).
        const float* __restrict__ erow = e + (size_t)bi * NN * ED;
#pragma unroll
        for (int it = 0; it < 16; it++) {
            const int f = t + it * 128;
            const int j = f >> 4;
            if (adj_s[j] != 0.0f) {
                const float4 v = __ldcs(reinterpret_cast<const float4*>(erow + f * 4));
                const u32 bx = __float_as_uint(v.x), by = __float_as_uint(v.y);
                const u32 bz = __float_as_uint(v.z), bw = __float_as_uint(v.w);
                const u32 hp0 = (bx >> 16) | (by & 0xFFFF0000u);
                const u32 hp1 = (bz >> 16) | (bw & 0xFFFF0000u);
                const float lx = v.x - __uint_as_float(bx & 0xFFFF0000u);
                const float ly = v.y - __uint_as_float(by & 0xFFFF0000u);
                const float lz = v.z - __uint_as_float(bz & 0xFFFF0000u);
                const float lw = v.w - __uint_as_float(bw & 0xFFFF0000u);
                const u32 lp0 = bf16x2_rn(lx, ly);
                const u32 lp1 = bf16x2_rn(lz, lw);
                const u32 off = (u32)(j * 144 + (f & 15) * 8);
                *reinterpret_cast<u64*>(sm + EH_OFF + off) =
                    (u64)hp0 | ((u64)hp1 << 32);
                *reinterpret_cast<u64*>(sm + EL_OFF + off) =
                    (u64)lp0 | ((u64)lp1 << 32);
            }
        }
        __syncthreads();

        // Hoist A-hi fragments: 2 jfrags x 4 kchunks.
        u32 AH[8][4];
#pragma unroll
        for (int kc = 0; kc < 4; kc++)
#pragma unroll
            for (int jf = 0; jf < 2; jf++)
                ldsm_x4(AH[kc * 2 + jf],
                        rowA + (u32)((j0 + jf * 16) * 144 + kc * 32));

        const float* __restrict__ c1b = g_c1 + (size_t)b * NN * MD;
        const float* __restrict__ c2b = g_c2 + (size_t)bi * MD;
        float* __restrict__ orow = out + (size_t)bi * NN * MD;

#pragma unroll
        for (int mc = 0; mc < 4; mc++) {
            float acc[8][4];
#pragma unroll
            for (int q = 0; q < 8; q++)
#pragma unroll
                for (int r = 0; r < 4; r++) acc[q][r] = 0.f;

#pragma unroll
            for (int kc = 0; kc < 4; kc++) {
                u32 BH[2][4], BL[2][4], AL[2][4];
                const u32 bBase = rowB + (u32)(kc * 16 * 272 + mc * 64);
#pragma unroll
                for (int nb = 0; nb < 2; nb++) {
                    ldsm_x4t(BH[nb], bBase + (u32)(nb * 32));
                    ldsm_x4t(BL[nb], bBase + (u32)(nb * 32) + (WL_OFF - WH_OFF));
                }
#pragma unroll
                for (int jf = 0; jf < 2; jf++)
                    ldsm_x4(AL[jf], rowA + (u32)((j0 + jf * 16) * 144 + kc * 32) +
                                        (EL_OFF - EH_OFF));
#pragma unroll
                for (int jf = 0; jf < 2; jf++) {
                    const u32* ah = AH[kc * 2 + jf];
#pragma unroll
                    for (int nb = 0; nb < 2; nb++) {
                        float* a0 = acc[jf * 4 + nb * 2 + 0];
                        float* a1 = acc[jf * 4 + nb * 2 + 1];
                        mma_bf16(a0, ah, BH[nb][0], BH[nb][1]);
                        mma_bf16(a1, ah, BH[nb][2], BH[nb][3]);
                        mma_bf16(a0, ah, BL[nb][0], BL[nb][1]);
                        mma_bf16(a1, ah, BL[nb][2], BL[nb][3]);
                        mma_bf16(a0, AL[jf], BH[nb][0], BH[nb][1]);
                        mma_bf16(a1, AL[jf], BH[nb][2], BH[nb][3]);
                    }
                }
            }

            // Epilogue for this m-chunk.
#pragma unroll
            for (int nf = 0; nf < 4; nf++) {
                const int m = mc * 32 + nf * 8 + 2 * tig;
                const float2 c2v =
                    *reinterpret_cast<const float2*>(&c2b[m]);
#pragma unroll
                for (int jf = 0; jf < 2; jf++) {
                    const float* a = acc[jf * 4 + nf];
                    const int j1 = j0 + jf * 16 + gid;
                    const int j2 = j1 + 8;
                    const float ad1 = adj_s[j1], ad2 = adj_s[j2];
                    const float2 c11 = *reinterpret_cast<const float2*>(
                        &c1b[(size_t)j1 * MD + m]);
                    const float2 c12 = *reinterpret_cast<const float2*>(
                        &c1b[(size_t)j2 * MD + m]);
                    __stcs(reinterpret_cast<float2*>(&orow[(size_t)j1 * MD + m]),
                           make_float2((a[0] + c11.x + c2v.x) * ad1,
                                       (a[1] + c11.y + c2v.y) * ad1));
                    __stcs(reinterpret_cast<float2*>(&orow[(size_t)j2 * MD + m]),
                           make_float2((a[2] + c12.x + c2v.x) * ad2,
                                       (a[3] + c12.y + c2v.y) * ad2));
                }
            }
        }
    }
}

extern "C" void kernel_launch(void* const* d_in, const int* in_sizes, int n_in,
                              void* d_out, int out_size) {
    const float* h    = (const float*)d_in[0];
    const float* e    = (const float*)d_in[1];
    const float* adj  = (const float*)d_in[2];
    const float* W    = (const float*)d_in[3];
    const float* bias = (const float*)d_in[4];
    float* out = (float*)d_out;

    cudaFuncSetAttribute(message_kernel,
                         cudaFuncAttributeMaxDynamicSharedMemorySize, SMEM_BYTES);

    precompute_kernel<<<256, 128>>>(h, W, bias);
    message_kernel<<<444, 128, SMEM_BYTES>>>(e, adj, W, out);
}

// round 5
// speedup vs baseline: 1.4168x; 1.4168x over previous
#include <cuda_runtime.h>
#include <cuda_bf16.h>
#include <cstdint>

#define BB 16
#define NN 128
#define HD 128
#define ED 64
#define MD 128

typedef unsigned long long u64;
typedef unsigned int u32;

// Scratch: c1[b,j,m] = h[b,j]@W1 + bias ; c2[b,i,m] = h[b,i]@W2
__device__ float g_c1[BB * NN * MD];
__device__ float g_c2[BB * NN * MD];

// ---------------- smem layout (dynamic, bytes) ----------------
// adj_s [0,512). e tile: 128 rows x 68 floats @512. stage: 2 x 32 x 132 floats.
#define ES_OFF 512
#define SJ 68                               // e row stride (floats)
#define ST_OFF (ES_OFF + 128 * SJ * 4)      // 35328
#define SM2 132                             // stage row stride (floats)
#define STAGE_FLOATS (32 * SM2)             // 4224
#define SMEM_BYTES (ST_OFF + 2 * STAGE_FLOATS * 4)  // 69120

__device__ __forceinline__ u32 f2tf32(float x) {
    u32 r;
    asm("cvt.rna.tf32.f32 %0, %1;" : "=r"(r) : "f"(x));
    return r;
}
__device__ __forceinline__ void mma_tf32(float c[4], const u32 a[4], u32 b0, u32 b1) {
    asm volatile(
        "mma.sync.aligned.m16n8k8.row.col.f32.tf32.tf32.f32 "
        "{%0,%1,%2,%3}, {%4,%5,%6,%7}, {%8,%9}, {%0,%1,%2,%3};"
        : "+f"(c[0]), "+f"(c[1]), "+f"(c[2]), "+f"(c[3])
        : "r"(a[0]), "r"(a[1]), "r"(a[2]), "r"(a[3]), "r"(b0), "r"(b1));
}

// ---------------- Kernel 1: precompute c1, c2 ----------------
__global__ __launch_bounds__(128) void precompute_kernel(
    const float* __restrict__ h, const float* __restrict__ W,
    const float* __restrict__ bias) {
    __shared__ float h_s[8 * 128];
    const int t = threadIdx.x;
    const int rb = blockIdx.x * 8;

#pragma unroll
    for (int q = 0; q < 8; q++)
        h_s[q * 128 + t] = h[(size_t)(rb + q) * HD + t];
    __syncthreads();

    float acc1[8], acc2[8];
#pragma unroll
    for (int r = 0; r < 8; r++) { acc1[r] = 0.f; acc2[r] = 0.f; }

#pragma unroll 4
    for (int k = 0; k < HD; k++) {
        const float w1 = W[(size_t)k * MD + t];
        const float w2 = W[(size_t)(HD + k) * MD + t];
#pragma unroll
        for (int r = 0; r < 8; r++) {
            const float hv = h_s[r * 128 + k];
            acc1[r] = fmaf(hv, w1, acc1[r]);
            acc2[r] = fmaf(hv, w2, acc2[r]);
        }
    }

    const float bv = bias[t];
#pragma unroll
    for (int r = 0; r < 8; r++) {
        g_c1[(size_t)(rb + r) * MD + t] = acc1[r] + bv;
        g_c2[(size_t)(rb + r) * MD + t] = acc2[r];
    }
}

// ---------------- Kernel 2: persistent tf32 message kernel ----------------
// Grid 444 (3 CTAs/SM), 256 threads (8 warps). Tile = (b,i):
//   D[j,m] = sum_k e[b,i,j,k] * W3[k,m]   (single-pass tf32 HMMA)
//   out[b,i,j,m] = (D + c1[b,j,m] + c2[b,i,m]) * adj[b,i,j]
// A-operand = W3^T held in registers (warp w owns m-rows [16w,16w+16)).
// B-operand = e fragments from smem. Epilogue staged through smem for
// fully coalesced c1 loads and out stores (one j-row of 512B per warp-instr).
__global__ __launch_bounds__(256, 3) void message_kernel(
    const float* __restrict__ e, const float* __restrict__ adj,
    const float* __restrict__ W, float* __restrict__ out) {
    extern __shared__ char smc[];
    float* adj_s = reinterpret_cast<float*>(smc);
    float* e_s = reinterpret_cast<float*>(smc + ES_OFF);
    u32* e_su = reinterpret_cast<u32*>(e_s);
    float* stg = reinterpret_cast<float*>(smc + ST_OFF);

    const int t = threadIdx.x;
    const int warp = t >> 5, lane = t & 31;
    const int g = lane >> 2, tg = lane & 3;
    const int mw = warp * 16;

    // Zero e tile once (finite-stale safety for adj-skipped rows).
    for (int i = t; i < 128 * SJ; i += 256) e_s[i] = 0.f;

    // W3^T A-fragments in registers (tf32). a0=[m=g][k=tg] etc.
    u32 afr[8][4];
#pragma unroll
    for (int kc = 0; kc < 8; kc++) {
        const int k0 = 2 * HD + kc * 8;
        afr[kc][0] = f2tf32(W[(size_t)(k0 + tg) * MD + mw + g]);
        afr[kc][1] = f2tf32(W[(size_t)(k0 + tg) * MD + mw + g + 8]);
        afr[kc][2] = f2tf32(W[(size_t)(k0 + tg + 4) * MD + mw + g]);
        afr[kc][3] = f2tf32(W[(size_t)(k0 + tg + 4) * MD + mw + g + 8]);
    }
    __syncthreads();

    for (int tile = blockIdx.x; tile < BB * NN; tile += gridDim.x) {
        const int bi = tile;
        const int b = tile >> 7;

        float adjv = 0.f;
        if (t < NN) adjv = __ldg(&adj[(size_t)bi * NN + t]);
        __syncthreads();  // previous tile's epilogue fully done
        if (t < NN) adj_s[t] = adjv;
        __syncthreads();

        // Stage active e rows -> tf32 smem tile [j][SJ].
        const float* __restrict__ erow = e + (size_t)bi * NN * ED;
#pragma unroll
        for (int i = 0; i < 8; i++) {
            const int f = t + i * 256;
            const int j = f >> 4;
            if (adj_s[j] != 0.0f) {
                const float4 v = __ldcs(reinterpret_cast<const float4*>(erow + f * 4));
                uint4 o;
                o.x = f2tf32(v.x); o.y = f2tf32(v.y);
                o.z = f2tf32(v.z); o.w = f2tf32(v.w);
                *reinterpret_cast<uint4*>(&e_su[j * SJ + (f & 15) * 4]) = o;
            }
        }
        __syncthreads();

        const float* __restrict__ c1b = g_c1 + (size_t)b * NN * MD;
        const float4 c2r = __ldg(reinterpret_cast<const float4*>(
            &g_c2[(size_t)bi * MD + 4 * lane]));
        float* __restrict__ orow = out + (size_t)bi * NN * MD;

#pragma unroll
        for (int bt = 0; bt < 4; bt++) {
            float* buf = stg + (bt & 1) * STAGE_FLOATS;
            // MMA: 4 j-chunks of 8 -> stage buffer (conflict-free STS.32).
#pragma unroll
            for (int q = 0; q < 4; q++) {
                const int jb = bt * 32 + q * 8;
                float acc[4] = {0.f, 0.f, 0.f, 0.f};
                const u32* br = &e_su[(jb + g) * SJ + tg];
#pragma unroll
                for (int kc = 0; kc < 8; kc++)
                    mma_tf32(acc, afr[kc], br[kc * 8], br[kc * 8 + 4]);
                const int r0 = (q * 8 + 2 * tg) * SM2 + mw + g;
                buf[r0] = acc[0];
                buf[r0 + SM2] = acc[1];
                buf[r0 + 8] = acc[2];
                buf[r0 + SM2 + 8] = acc[3];
            }
            // Epilogue of previous batch (reads other buffer).
            if (bt > 0) {
                const int pb = bt - 1;
                const float* pbuf = stg + (pb & 1) * STAGE_FLOATS;
#pragma unroll
                for (int i = 0; i < 4; i++) {
                    const int jl = i * 8 + warp;
                    const int j = pb * 32 + jl;
                    const float4 d = *reinterpret_cast<const float4*>(
                        &pbuf[jl * SM2 + 4 * lane]);
                    const float4 c1 = __ldg(reinterpret_cast<const float4*>(
                        &c1b[(size_t)j * MD + 4 * lane]));
                    const float a = adj_s[j];
                    __stcs(reinterpret_cast<float4*>(&orow[(size_t)j * MD + 4 * lane]),
                           make_float4((d.x + c1.x + c2r.x) * a,
                                       (d.y + c1.y + c2r.y) * a,
                                       (d.z + c1.z + c2r.z) * a,
                                       (d.w + c1.w + c2r.w) * a));
                }
            }
            __syncthreads();
        }
        // Final batch epilogue.
        {
            const float* pbuf = stg + STAGE_FLOATS;  // bt=3 -> buf 1
#pragma unroll
            for (int i = 0; i < 4; i++) {
                const int jl = i * 8 + warp;
                const int j = 96 + jl;
                const float4 d = *reinterpret_cast<const float4*>(
                    &pbuf[jl * SM2 + 4 * lane]);
                const float4 c1 = __ldg(reinterpret_cast<const float4*>(
                    &c1b[(size_t)j * MD + 4 * lane]));
                const float a = adj_s[j];
                __stcs(reinterpret_cast<float4*>(&orow[(size_t)j * MD + 4 * lane]),
                       make_float4((d.x + c1.x + c2r.x) * a,
                                   (d.y + c1.y + c2r.y) * a,
                                   (d.z + c1.z + c2r.z) * a,
                                   (d.w + c1.w + c2r.w) * a));
            }
        }
    }
}

extern "C" void kernel_launch(void* const* d_in, const int* in_sizes, int n_in,
                              void* d_out, int out_size) {
    const float* h    = (const float*)d_in[0];
    const float* e    = (const float*)d_in[1];
    const float* adj  = (const float*)d_in[2];
    const float* W    = (const float*)d_in[3];
    const float* bias = (const float*)d_in[4];
    float* out = (float*)d_out;

    cudaFuncSetAttribute(message_kernel,
                         cudaFuncAttributeMaxDynamicSharedMemorySize, SMEM_BYTES);

    precompute_kernel<<<256, 128>>>(h, W, bias);
    message_kernel<<<444, 256, SMEM_BYTES>>>(e, adj, W, out);
}